// round 14
// baseline (speedup 1.0000x reference)
#include <cuda_runtime.h>
#include <cuda_fp16.h>
#include <cstdint>
#include <math.h>

#define B_ROWS 8192
#define F_DIM  2048
#define F2_DIM 4096
#define DB 512
#define DA 256
#define DE 256
#define DM 512
#define DS 512

// ---- device scratch (allocation forbidden) ----
__device__ __align__(256) __half g_comb[B_ROWS * F_DIM];     // combined, later fused (fp16)
__device__ __align__(256) __half g_act [B_ROWS * F2_DIM];    // layer-1 / mlp1 outputs
__device__ __align__(256) __half g_ga  [B_ROWS * F_DIM];     // gate2 out, later mlp2 out
__device__ __align__(256) __half g_gb  [B_ROWS * F_DIM];     // tr2 out
__device__ __align__(256) __half g_wq[4 * F_DIM * F_DIM];    // slots: gate_w1, tr_w1, gate_w2, tr_w2
__device__ __align__(256) __half g_w1h[F2_DIM * F_DIM];
__device__ __align__(256) __half g_w2h[F_DIM * F2_DIM];
__device__ float g_partials[4 * 64];
__device__ float g_scale[4];

// ---- helpers (baseline PTX only) ----
__device__ __forceinline__ uint32_t smem_u32(const void* p) {
    uint32_t a;
    asm("{ .reg .u64 t; cvta.to.shared.u64 t, %1; cvt.u32.u64 %0, t; }" : "=r"(a) : "l"(p));
    return a;
}
__device__ __forceinline__ uint32_t sw128(uint32_t x) { return x ^ ((x >> 3) & 0x70); }
__device__ __forceinline__ void cp16(uint32_t dst, const void* src) {
    asm volatile("cp.async.cg.shared.global [%0], [%1], 16;\n" :: "r"(dst), "l"(src) : "memory");
}
__device__ __forceinline__ void cp_commit() { asm volatile("cp.async.commit_group;\n" ::: "memory"); }
template <int N> __device__ __forceinline__ void cp_wait() {
    asm volatile("cp.async.wait_group %0;\n" :: "n"(N) : "memory");
}
__device__ __forceinline__ void ldsm4(uint32_t* r, uint32_t a) {
    asm volatile("ldmatrix.sync.aligned.m8n8.x4.shared.b16 {%0,%1,%2,%3}, [%4];"
        : "=r"(r[0]), "=r"(r[1]), "=r"(r[2]), "=r"(r[3]) : "r"(a));
}
__device__ __forceinline__ void mma_f16(float* c, const uint32_t* a, uint32_t b0, uint32_t b1) {
    asm volatile("mma.sync.aligned.m16n8k16.row.col.f32.f16.f16.f32 "
        "{%0,%1,%2,%3}, {%4,%5,%6,%7}, {%8,%9}, {%0,%1,%2,%3};"
        : "+f"(c[0]), "+f"(c[1]), "+f"(c[2]), "+f"(c[3])
        : "r"(a[0]), "r"(a[1]), "r"(a[2]), "r"(a[3]), "r"(b0), "r"(b1));
}
__device__ __forceinline__ float gelu_erf(float h) {
    return 0.5f * h * (1.0f + erff(h * 0.70710678f));
}
__device__ __forceinline__ uint32_t packh2(float a, float b) {
    __half2 v; v.x = __float2half_rn(a); v.y = __float2half_rn(b);
    return *reinterpret_cast<uint32_t*>(&v);
}

// ---- fp16 GEMM, CTA tile 256x128, 512 threads, warp tile 64x32 ----
#define TILE_M 256
#define TILE_N 128
#define TILE_K 64
#define GTHREADS 512
#define STAGE_BYTES (TILE_M * 128 + TILE_N * 128)   // 48KB
#define STAGES 3
#define GEMM_SMEM_DYN (STAGES * STAGE_BYTES + 1024)

__device__ __forceinline__ void load_tiles(uint32_t sa, uint32_t sb,
        const __half* Ab, const __half* Bt, int m0, int k0, int lda, int K, int tid) {
    const char* ab = (const char*)(Ab + (size_t)m0 * lda + k0);
    const char* bb = (const char*)(Bt + k0);
    size_t ra = (size_t)lda * 2, rb = (size_t)K * 2;
#pragma unroll
    for (int i = 0; i < 4; i++) {               // A: 256 rows * 8 chunks = 2048
        int t = tid + i * GTHREADS, row = t >> 3, ch = t & 7;
        cp16(sa + sw128(row * 128 + ch * 16), ab + (size_t)row * ra + ch * 16);
    }
#pragma unroll
    for (int i = 0; i < 2; i++) {               // B: 128 rows * 8 chunks = 1024
        int t = tid + i * GTHREADS, row = t >> 3, ch = t & 7;
        cp16(sb + sw128(row * 128 + ch * 16), bb + (size_t)row * rb + ch * 16);
    }
}

// EPI 0: gelu -> fp16 at GLOBAL col, stride outStride; EPI 1: linear -> fp16 at LOCAL col, stride F_DIM
template <int EPI>
__global__ void __launch_bounds__(GTHREADS, 1)
gemm_f16(const __half* A, int lda, int aoffHalf,
         const __half* Bbase, int K,
         const float* scales,
         const float* __restrict__ bias0, const float* __restrict__ bias1,
         __half* outF0, __half* outF1, __half* outH, int outStride) {
    extern __shared__ char smem[];
    uint32_t sbase = (smem_u32(smem) + 1023) & ~1023u;
    int tid = threadIdx.x, wid = tid >> 5, lane = tid & 31;
    int n0 = blockIdx.x * TILE_N, m0 = blockIdx.y * TILE_M;
    int half = (n0 >= F_DIM) ? 1 : 0;
    const __half* Ab = A + (half ? (size_t)aoffHalf : 0);
    const __half* Bt = Bbase + (size_t)n0 * K;
    const float* bias = half ? bias1 : bias0;
    __half* outF = half ? outF1 : outF0;
    int colBiasOff = half * F_DIM;
    int wm = wid & 3, wn = wid >> 2;     // 4 M-slices of 64, 4 N-slices of 32
    const int iters = K / TILE_K;

    for (int p = 0; p < 2 && p < iters; ++p) {
        uint32_t st = sbase + p * STAGE_BYTES;
        load_tiles(st, st + TILE_M * 128, Ab, Bt, m0, p * TILE_K, lda, K, tid);
        cp_commit();
    }

    float acc[4][4][4];
#pragma unroll
    for (int i = 0; i < 4; i++)
#pragma unroll
        for (int j = 0; j < 4; j++)
#pragma unroll
            for (int k = 0; k < 4; k++) acc[i][j][k] = 0.f;

    int q = lane >> 3, r = lane & 7;
    int aRow = wm * 64 + r + (q & 1) * 8;
    int aCol = (q >> 1) * 16;
    int bRow = wn * 32 + r + (q >> 1) * 8;
    int bCol = (q & 1) * 16;

    for (int it = 0; it < iters; ++it) {
        cp_wait<1>();
        __syncthreads();
        if (it + 2 < iters) {
            uint32_t st = sbase + ((it + 2) % STAGES) * STAGE_BYTES;
            load_tiles(st, st + TILE_M * 128, Ab, Bt, m0, (it + 2) * TILE_K, lda, K, tid);
        }
        cp_commit();
        uint32_t sA = sbase + (it % STAGES) * STAGE_BYTES;
        uint32_t sB = sA + TILE_M * 128;
#pragma unroll
        for (int ks = 0; ks < 4; ++ks) {
            uint32_t a[4][4], b[2][4];
#pragma unroll
            for (int mi = 0; mi < 4; ++mi)
                ldsm4(a[mi], sA + sw128((aRow + mi * 16) * 128 + aCol + ks * 32));
#pragma unroll
            for (int nj = 0; nj < 2; ++nj)
                ldsm4(b[nj], sB + sw128((bRow + nj * 16) * 128 + bCol + ks * 32));
#pragma unroll
            for (int mi = 0; mi < 4; ++mi)
#pragma unroll
                for (int n8 = 0; n8 < 4; ++n8)
                    mma_f16(acc[mi][n8], a[mi],
                            b[n8 >> 1][(n8 & 1) * 2], b[n8 >> 1][(n8 & 1) * 2 + 1]);
        }
    }

    float sc = scales ? scales[half] : 1.0f;
    int group = lane >> 2, tg = lane & 3;
#pragma unroll
    for (int mi = 0; mi < 4; ++mi) {
#pragma unroll
        for (int n8 = 0; n8 < 4; ++n8) {
            int row = m0 + wm * 64 + mi * 16 + group;
            int col = n0 + wn * 32 + n8 * 8 + tg * 2;
            int cl = col - colBiasOff;
            float bb0 = bias[cl], bb1 = bias[cl + 1];
            float y0 = fmaf(sc, acc[mi][n8][0], bb0);
            float y1 = fmaf(sc, acc[mi][n8][1], bb1);
            float y2 = fmaf(sc, acc[mi][n8][2], bb0);
            float y3 = fmaf(sc, acc[mi][n8][3], bb1);
            if (EPI == 0) {
                *(uint32_t*)&outH[(size_t)row * outStride + col]       = packh2(gelu_erf(y0), gelu_erf(y1));
                *(uint32_t*)&outH[(size_t)(row + 8) * outStride + col] = packh2(gelu_erf(y2), gelu_erf(y3));
            } else {
                *(uint32_t*)&outF[(size_t)row * F_DIM + cl]       = packh2(y0, y1);
                *(uint32_t*)&outF[(size_t)(row + 8) * F_DIM + cl] = packh2(y2, y3);
            }
        }
    }
}

// ---- elementwise kernels ----
__device__ __forceinline__ float warpSum(float x) {
#pragma unroll
    for (int o = 16; o > 0; o >>= 1) x += __shfl_xor_sync(0xffffffffu, x, o);
    return x;
}

__global__ void absmean_partial(const float* w0, const float* w1, const float* w2, const float* w3) {
    const float* w = (blockIdx.y == 0) ? w0 : (blockIdx.y == 1) ? w1 : (blockIdx.y == 2) ? w2 : w3;
    const int chunk = (F_DIM * F_DIM) / 64;
    int base = blockIdx.x * chunk;
    float s = 0.f;
    for (int i = threadIdx.x; i < chunk; i += 256) s += fabsf(w[base + i]);
    __shared__ float red[8];
    s = warpSum(s);
    int wd = threadIdx.x >> 5, ln = threadIdx.x & 31;
    if (ln == 0) red[wd] = s;
    __syncthreads();
    if (wd == 0) {
        float v = (ln < 8) ? red[ln] : 0.f;
        v = warpSum(v);
        if (ln == 0) g_partials[blockIdx.y * 64 + blockIdx.x] = v;
    }
}

__global__ void quantize_ternary(const float* w0, const float* w1, const float* w2, const float* w3,
                                 __half* __restrict__ kq) {
    int slot = blockIdx.y;
    const float* w = (slot == 0) ? w0 : (slot == 1) ? w1 : (slot == 2) ? w2 : w3;
    __half* dst = kq + (size_t)slot * F_DIM * F_DIM;
    float sum = 0.f;
#pragma unroll
    for (int i = 0; i < 64; i++) sum += g_partials[slot * 64 + i];
    float s = sum * (1.0f / (float)(F_DIM * F_DIM));
    if (blockIdx.x == 0 && threadIdx.x == 0) g_scale[slot] = s;
    float inv = 1.0f / (s + 1e-5f);
    const int n4 = (F_DIM * F_DIM) / 4;
    int stride = gridDim.x * blockDim.x;
    for (int i = blockIdx.x * blockDim.x + threadIdx.x; i < n4; i += stride) {
        float4 v = reinterpret_cast<const float4*>(w)[i];
        float q0 = rintf(fminf(fmaxf(v.x * inv, -1.f), 1.f));
        float q1 = rintf(fminf(fmaxf(v.y * inv, -1.f), 1.f));
        float q2 = rintf(fminf(fmaxf(v.z * inv, -1.f), 1.f));
        float q3 = rintf(fminf(fmaxf(v.w * inv, -1.f), 1.f));
        uint2 u; u.x = packh2(q0, q1); u.y = packh2(q2, q3);
        reinterpret_cast<uint2*>(dst)[i] = u;
    }
}

__global__ void convert_w(const float* __restrict__ wa, __half* __restrict__ ha,
                          const float* __restrict__ wb, __half* __restrict__ hb, int n4) {
    const float* w = blockIdx.y ? wb : wa;
    __half* h = blockIdx.y ? hb : ha;
    int stride = gridDim.x * blockDim.x;
    for (int i = blockIdx.x * blockDim.x + threadIdx.x; i < n4; i += stride) {
        float4 v = reinterpret_cast<const float4*>(w)[i];
        uint2 u; u.x = packh2(v.x, v.y); u.y = packh2(v.z, v.w);
        reinterpret_cast<uint2*>(h)[i] = u;
    }
}

__global__ void build_combined(const float* zb, const float* za, const float* ze,
                               const float* zm, const float* zs, __half* __restrict__ ch) {
    int idx = blockIdx.x * 256 + threadIdx.x;
    int r = idx >> 9;
    int c4 = (idx & 511) * 4;
    const float* src; int off;
    if      (c4 < DB)                { src = zb; off = r * DB + c4; }
    else if (c4 < DB + DA)           { src = za; off = r * DA + (c4 - DB); }
    else if (c4 < DB + DA + DE)      { src = ze; off = r * DE + (c4 - DB - DA); }
    else if (c4 < DB + DA + DE + DM) { src = zm; off = r * DM + (c4 - DB - DA - DE); }
    else                             { src = zs; off = r * DS + (c4 - DB - DA - DE - DM); }
    float4 v = *reinterpret_cast<const float4*>(src + off);
    uint2 u;
    u.x = packh2(v.x, v.y);
    u.y = packh2(v.z, v.w);
    *reinterpret_cast<uint2*>(&ch[(size_t)r * F_DIM + c4]) = u;
}

// fused = LN(sigmoid(1.2 g) * t) -> fp16 (single buffer: mlp input AND residual)
__global__ void fused_sig_ln(const __half* __restrict__ g, const __half* __restrict__ t,
                             const float* __restrict__ lg, const float* __restrict__ lb,
                             __half* __restrict__ fh) {
    int row = blockIdx.x;
    size_t base = (size_t)row * F_DIM;
    float v[8], s1 = 0.f, s2 = 0.f;
#pragma unroll
    for (int i = 0; i < 8; i++) {
        int c = i * 256 + threadIdx.x;
        float gg = __half2float(g[base + c]), tt = __half2float(t[base + c]);
        float f = tt / (1.0f + expf(-1.2f * gg));
        v[i] = f; s1 += f; s2 += f * f;
    }
    __shared__ float rs[8], rq[8];
    int wd = threadIdx.x >> 5, ln = threadIdx.x & 31;
    float a = warpSum(s1), b = warpSum(s2);
    if (ln == 0) { rs[wd] = a; rq[wd] = b; }
    __syncthreads();
    if (wd == 0) {
        float x = (ln < 8) ? rs[ln] : 0.f;
        float y = (ln < 8) ? rq[ln] : 0.f;
        x = warpSum(x); y = warpSum(y);
        if (ln == 0) { rs[0] = x; rq[0] = y; }
    }
    __syncthreads();
    float mean = rs[0] * (1.0f / F_DIM);
    float var = rq[0] * (1.0f / F_DIM) - mean * mean;
    float inv = rsqrtf(var + 1e-5f);
#pragma unroll
    for (int i = 0; i < 8; i++) {
        int c = i * 256 + threadIdx.x;
        float y = (v[i] - mean) * inv * lg[c] + lb[c];
        fh[base + c] = __float2half_rn(y);
    }
}

__global__ void final_ln(const __half* __restrict__ fused, const __half* __restrict__ mlp,
                         const float* __restrict__ lg, const float* __restrict__ lb,
                         float* __restrict__ out) {
    int row = blockIdx.x;
    size_t base = (size_t)row * F_DIM;
    float v[8], s1 = 0.f, s2 = 0.f;
#pragma unroll
    for (int i = 0; i < 8; i++) {
        int c = i * 256 + threadIdx.x;
        float f = __half2float(fused[base + c]) + __half2float(mlp[base + c]);
        v[i] = f; s1 += f; s2 += f * f;
    }
    __shared__ float rs[8], rq[8];
    int wd = threadIdx.x >> 5, ln = threadIdx.x & 31;
    float a = warpSum(s1), b = warpSum(s2);
    if (ln == 0) { rs[wd] = a; rq[wd] = b; }
    __syncthreads();
    if (wd == 0) {
        float x = (ln < 8) ? rs[ln] : 0.f;
        float y = (ln < 8) ? rq[ln] : 0.f;
        x = warpSum(x); y = warpSum(y);
        if (ln == 0) { rs[0] = x; rq[0] = y; }
    }
    __syncthreads();
    float mean = rs[0] * (1.0f / F_DIM);
    float var = rq[0] * (1.0f / F_DIM) - mean * mean;
    float inv = rsqrtf(var + 1e-5f);
#pragma unroll
    for (int i = 0; i < 8; i++) {
        int c = i * 256 + threadIdx.x;
        out[base + c] = (v[i] - mean) * inv * lg[c] + lb[c];
    }
}

// ---- launch ----
extern "C" void kernel_launch(void* const* d_in, const int* in_sizes, int n_in,
                              void* d_out, int out_size) {
    (void)in_sizes; (void)n_in; (void)out_size;
    const float* zb = (const float*)d_in[0];
    const float* za = (const float*)d_in[1];
    const float* ze = (const float*)d_in[2];
    const float* zm = (const float*)d_in[3];
    const float* zs = (const float*)d_in[4];
    const float* gate_w1 = (const float*)d_in[5];
    const float* gate_b1 = (const float*)d_in[6];
    const float* gate_w2 = (const float*)d_in[7];
    const float* gate_b2 = (const float*)d_in[8];
    const float* tr_w1 = (const float*)d_in[9];
    const float* tr_b1 = (const float*)d_in[10];
    const float* tr_w2 = (const float*)d_in[11];
    const float* tr_b2 = (const float*)d_in[12];
    const float* mlp_w1 = (const float*)d_in[13];
    const float* mlp_b1 = (const float*)d_in[14];
    const float* mlp_w2 = (const float*)d_in[15];
    const float* mlp_b2 = (const float*)d_in[16];
    const float* ln1_g = (const float*)d_in[17];
    const float* ln1_b = (const float*)d_in[18];
    const float* ln2_g = (const float*)d_in[19];
    const float* ln2_b = (const float*)d_in[20];
    float* out = (float*)d_out;

    __half *ch, *ah, *ga, *gb, *wqb, *w1h, *w2h;
    float *scb;
    cudaGetSymbolAddress((void**)&ch,  g_comb);
    cudaGetSymbolAddress((void**)&ah,  g_act);
    cudaGetSymbolAddress((void**)&ga,  g_ga);
    cudaGetSymbolAddress((void**)&gb,  g_gb);
    cudaGetSymbolAddress((void**)&wqb, g_wq);
    cudaGetSymbolAddress((void**)&w1h, g_w1h);
    cudaGetSymbolAddress((void**)&w2h, g_w2h);
    cudaGetSymbolAddress((void**)&scb, g_scale);

    cudaFuncSetAttribute(gemm_f16<0>, cudaFuncAttributeMaxDynamicSharedMemorySize, GEMM_SMEM_DYN);
    cudaFuncSetAttribute(gemm_f16<1>, cudaFuncAttributeMaxDynamicSharedMemorySize, GEMM_SMEM_DYN);

    // weight prep (slot order: gate_w1, tr_w1, gate_w2, tr_w2)
    absmean_partial<<<dim3(64, 4), 256>>>(gate_w1, tr_w1, gate_w2, tr_w2);
    quantize_ternary<<<dim3(128, 4), 256>>>(gate_w1, tr_w1, gate_w2, tr_w2, wqb);
    convert_w<<<dim3(512, 2), 256>>>(mlp_w1, w1h, mlp_w2, w2h, (F2_DIM * F_DIM) / 4);
    build_combined<<<(B_ROWS * 512) / 256, 256>>>(zb, za, ze, zm, zs, ch);

    dim3 gDual(F2_DIM / TILE_N, B_ROWS / TILE_M);  // (32, 32)
    dim3 gHalf(F_DIM / TILE_N, B_ROWS / TILE_M);   // (16, 32)

    // layer-1 dual: gate1 + tr1 (shared A; stacked weight slots 0-1; gelu -> act [8192,4096])
    gemm_f16<0><<<gDual, GTHREADS, GEMM_SMEM_DYN>>>(ch, F_DIM, 0, wqb, F_DIM,
        scb + 0, gate_b1, tr_b1, nullptr, nullptr, ah, F2_DIM);
    // layer-2 dual: gate2 + tr2 (per-half A window; slots 2-3; fp16 -> ga / gb)
    gemm_f16<1><<<gDual, GTHREADS, GEMM_SMEM_DYN>>>(ah, F2_DIM, F_DIM,
        wqb + 2 * (size_t)F_DIM * F_DIM, F_DIM,
        scb + 2, gate_b2, tr_b2, ga, gb, nullptr, 0);
    // sigmoid-gate fuse + ln1 -> fp16 fused (reuses comb buffer; serves mlp input AND residual)
    fused_sig_ln<<<B_ROWS, 256>>>(ga, gb, ln1_g, ln1_b, ch);
    // mlp1 (gelu -> act [8192,4096])
    gemm_f16<0><<<gDual, GTHREADS, GEMM_SMEM_DYN>>>(ch, F_DIM, 0, w1h, F_DIM,
        nullptr, mlp_b1, mlp_b1 + F_DIM, nullptr, nullptr, ah, F2_DIM);
    // mlp2 (K=4096, fp16 -> ga)
    gemm_f16<1><<<gHalf, GTHREADS, GEMM_SMEM_DYN>>>(ah, F2_DIM, 0, w2h, F2_DIM,
        nullptr, mlp_b2, mlp_b2, ga, ga, nullptr, 0);
    // residual + ln2
    final_ln<<<B_ROWS, 256>>>(ch, ga, ln2_g, ln2_b, out);
}

// round 15
// speedup vs baseline: 1.0835x; 1.0835x over previous
#include <cuda_runtime.h>
#include <cuda_fp16.h>
#include <cstdint>
#include <math.h>

#define B_ROWS 8192
#define F_DIM  2048
#define F2_DIM 4096
#define DB 512
#define DA 256
#define DE 256
#define DM 512
#define DS 512

// ---- device scratch (allocation forbidden) ----
__device__ __align__(256) __half g_comb[B_ROWS * F_DIM];     // combined, later fused (fp16)
__device__ __align__(256) __half g_act [B_ROWS * F2_DIM];    // layer-1 / mlp1 outputs
__device__ __align__(256) __half g_ga  [B_ROWS * F_DIM];     // gate2 out, later mlp2 out
__device__ __align__(256) __half g_gb  [B_ROWS * F_DIM];     // tr2 out
__device__ __align__(256) __half g_wq[4 * F_DIM * F_DIM];    // slots: gate_w1, tr_w1, gate_w2, tr_w2
__device__ __align__(256) __half g_w1h[F2_DIM * F_DIM];
__device__ __align__(256) __half g_w2h[F_DIM * F2_DIM];
__device__ float g_partials[4 * 64];
__device__ float g_scale[4];

// ---- helpers (baseline PTX only) ----
__device__ __forceinline__ uint32_t smem_u32(const void* p) {
    uint32_t a;
    asm("{ .reg .u64 t; cvta.to.shared.u64 t, %1; cvt.u32.u64 %0, t; }" : "=r"(a) : "l"(p));
    return a;
}
__device__ __forceinline__ uint32_t sw128(uint32_t x) { return x ^ ((x >> 3) & 0x70); }
__device__ __forceinline__ void cp16(uint32_t dst, const void* src) {
    asm volatile("cp.async.cg.shared.global [%0], [%1], 16;\n" :: "r"(dst), "l"(src) : "memory");
}
__device__ __forceinline__ void cp_commit() { asm volatile("cp.async.commit_group;\n" ::: "memory"); }
template <int N> __device__ __forceinline__ void cp_wait() {
    asm volatile("cp.async.wait_group %0;\n" :: "n"(N) : "memory");
}
__device__ __forceinline__ void ldsm4(uint32_t* r, uint32_t a) {
    asm volatile("ldmatrix.sync.aligned.m8n8.x4.shared.b16 {%0,%1,%2,%3}, [%4];"
        : "=r"(r[0]), "=r"(r[1]), "=r"(r[2]), "=r"(r[3]) : "r"(a));
}
__device__ __forceinline__ void mma_f16(float* c, const uint32_t* a, uint32_t b0, uint32_t b1) {
    asm volatile("mma.sync.aligned.m16n8k16.row.col.f32.f16.f16.f32 "
        "{%0,%1,%2,%3}, {%4,%5,%6,%7}, {%8,%9}, {%0,%1,%2,%3};"
        : "+f"(c[0]), "+f"(c[1]), "+f"(c[2]), "+f"(c[3])
        : "r"(a[0]), "r"(a[1]), "r"(a[2]), "r"(a[3]), "r"(b0), "r"(b1));
}
__device__ __forceinline__ float gelu_erf(float h) {
    return 0.5f * h * (1.0f + erff(h * 0.70710678f));
}
__device__ __forceinline__ uint32_t packh2(float a, float b) {
    __half2 v; v.x = __float2half_rn(a); v.y = __float2half_rn(b);
    return *reinterpret_cast<uint32_t*>(&v);
}

// ---- fp16 GEMM, CTA tile 128x128, 256 threads, occ 2 (the R13-proven config) ----
#define TILE_M 128
#define TILE_N 128
#define TILE_K 64
#define STAGE_BYTES (TILE_M * 128 + TILE_N * 128)   // 32KB
#define STAGES 3
#define GEMM_SMEM_DYN (STAGES * STAGE_BYTES + 1024)

__device__ __forceinline__ void load_tiles(uint32_t sa, uint32_t sb,
        const __half* Ab, const __half* Bt, int m0, int k0, int lda, int K, int tid) {
    const char* ab = (const char*)(Ab + (size_t)m0 * lda + k0);
    const char* bb = (const char*)(Bt + k0);
    size_t ra = (size_t)lda * 2, rb = (size_t)K * 2;
#pragma unroll
    for (int i = 0; i < 4; i++) {
        int t = tid + i * 256, row = t >> 3, ch = t & 7;
        cp16(sa + sw128(row * 128 + ch * 16), ab + (size_t)row * ra + ch * 16);
    }
#pragma unroll
    for (int i = 0; i < 4; i++) {
        int t = tid + i * 256, row = t >> 3, ch = t & 7;
        cp16(sb + sw128(row * 128 + ch * 16), bb + (size_t)row * rb + ch * 16);
    }
}

// EPI 0: gelu -> fp16 at GLOBAL col, stride outStride; EPI 1: linear -> fp16 at LOCAL col, stride F_DIM
template <int EPI>
__global__ void __launch_bounds__(256, 2)
gemm_f16(const __half* A, int lda, int aoffHalf,
         const __half* Bbase, int K,
         const float* scales,
         const float* __restrict__ bias0, const float* __restrict__ bias1,
         __half* outF0, __half* outF1, __half* outH, int outStride) {
    extern __shared__ char smem[];
    uint32_t sbase = (smem_u32(smem) + 1023) & ~1023u;
    int tid = threadIdx.x, wid = tid >> 5, lane = tid & 31;
    int n0 = blockIdx.x * TILE_N, m0 = blockIdx.y * TILE_M;
    int half = (n0 >= F_DIM) ? 1 : 0;
    const __half* Ab = A + (half ? (size_t)aoffHalf : 0);
    const __half* Bt = Bbase + (size_t)n0 * K;
    const float* bias = half ? bias1 : bias0;
    __half* outF = half ? outF1 : outF0;
    int colBiasOff = half * F_DIM;
    int wm = wid & 1, wn = wid >> 1;
    const int iters = K / TILE_K;

    for (int p = 0; p < 2 && p < iters; ++p) {
        uint32_t st = sbase + p * STAGE_BYTES;
        load_tiles(st, st + TILE_M * 128, Ab, Bt, m0, p * TILE_K, lda, K, tid);
        cp_commit();
    }

    float acc[4][4][4];
#pragma unroll
    for (int i = 0; i < 4; i++)
#pragma unroll
        for (int j = 0; j < 4; j++)
#pragma unroll
            for (int k = 0; k < 4; k++) acc[i][j][k] = 0.f;

    int q = lane >> 3, r = lane & 7;
    int aRow = wm * 64 + r + (q & 1) * 8;
    int aCol = (q >> 1) * 16;
    int bRow = wn * 32 + r + (q >> 1) * 8;
    int bCol = (q & 1) * 16;

    for (int it = 0; it < iters; ++it) {
        cp_wait<1>();
        __syncthreads();
        if (it + 2 < iters) {
            uint32_t st = sbase + ((it + 2) % STAGES) * STAGE_BYTES;
            load_tiles(st, st + TILE_M * 128, Ab, Bt, m0, (it + 2) * TILE_K, lda, K, tid);
        }
        cp_commit();
        uint32_t sA = sbase + (it % STAGES) * STAGE_BYTES;
        uint32_t sB = sA + TILE_M * 128;
#pragma unroll
        for (int ks = 0; ks < 4; ++ks) {
            uint32_t a[4][4], b[2][4];
#pragma unroll
            for (int mi = 0; mi < 4; ++mi)
                ldsm4(a[mi], sA + sw128((aRow + mi * 16) * 128 + aCol + ks * 32));
#pragma unroll
            for (int nj = 0; nj < 2; ++nj)
                ldsm4(b[nj], sB + sw128((bRow + nj * 16) * 128 + bCol + ks * 32));
#pragma unroll
            for (int mi = 0; mi < 4; ++mi)
#pragma unroll
                for (int n8 = 0; n8 < 4; ++n8)
                    mma_f16(acc[mi][n8], a[mi],
                            b[n8 >> 1][(n8 & 1) * 2], b[n8 >> 1][(n8 & 1) * 2 + 1]);
        }
    }

    float sc = scales ? scales[half] : 1.0f;
    int group = lane >> 2, tg = lane & 3;
#pragma unroll
    for (int mi = 0; mi < 4; ++mi) {
#pragma unroll
        for (int n8 = 0; n8 < 4; ++n8) {
            int row = m0 + wm * 64 + mi * 16 + group;
            int col = n0 + wn * 32 + n8 * 8 + tg * 2;
            int cl = col - colBiasOff;
            float bb0 = bias[cl], bb1 = bias[cl + 1];
            float y0 = fmaf(sc, acc[mi][n8][0], bb0);
            float y1 = fmaf(sc, acc[mi][n8][1], bb1);
            float y2 = fmaf(sc, acc[mi][n8][2], bb0);
            float y3 = fmaf(sc, acc[mi][n8][3], bb1);
            if (EPI == 0) {
                *(uint32_t*)&outH[(size_t)row * outStride + col]       = packh2(gelu_erf(y0), gelu_erf(y1));
                *(uint32_t*)&outH[(size_t)(row + 8) * outStride + col] = packh2(gelu_erf(y2), gelu_erf(y3));
            } else {
                *(uint32_t*)&outF[(size_t)row * F_DIM + cl]       = packh2(y0, y1);
                *(uint32_t*)&outF[(size_t)(row + 8) * F_DIM + cl] = packh2(y2, y3);
            }
        }
    }
}

// ---- elementwise kernels ----
__device__ __forceinline__ float warpSum(float x) {
#pragma unroll
    for (int o = 16; o > 0; o >>= 1) x += __shfl_xor_sync(0xffffffffu, x, o);
    return x;
}

__global__ void absmean_partial(const float* w0, const float* w1, const float* w2, const float* w3) {
    const float* w = (blockIdx.y == 0) ? w0 : (blockIdx.y == 1) ? w1 : (blockIdx.y == 2) ? w2 : w3;
    const int chunk = (F_DIM * F_DIM) / 64;
    int base = blockIdx.x * chunk;
    float s = 0.f;
    for (int i = threadIdx.x; i < chunk; i += 256) s += fabsf(w[base + i]);
    __shared__ float red[8];
    s = warpSum(s);
    int wd = threadIdx.x >> 5, ln = threadIdx.x & 31;
    if (ln == 0) red[wd] = s;
    __syncthreads();
    if (wd == 0) {
        float v = (ln < 8) ? red[ln] : 0.f;
        v = warpSum(v);
        if (ln == 0) g_partials[blockIdx.y * 64 + blockIdx.x] = v;
    }
}

__global__ void quantize_ternary(const float* w0, const float* w1, const float* w2, const float* w3,
                                 __half* __restrict__ kq) {
    int slot = blockIdx.y;
    const float* w = (slot == 0) ? w0 : (slot == 1) ? w1 : (slot == 2) ? w2 : w3;
    __half* dst = kq + (size_t)slot * F_DIM * F_DIM;
    float sum = 0.f;
#pragma unroll
    for (int i = 0; i < 64; i++) sum += g_partials[slot * 64 + i];
    float s = sum * (1.0f / (float)(F_DIM * F_DIM));
    if (blockIdx.x == 0 && threadIdx.x == 0) g_scale[slot] = s;
    float inv = 1.0f / (s + 1e-5f);
    const int n4 = (F_DIM * F_DIM) / 4;
    int stride = gridDim.x * blockDim.x;
    for (int i = blockIdx.x * blockDim.x + threadIdx.x; i < n4; i += stride) {
        float4 v = reinterpret_cast<const float4*>(w)[i];
        float q0 = rintf(fminf(fmaxf(v.x * inv, -1.f), 1.f));
        float q1 = rintf(fminf(fmaxf(v.y * inv, -1.f), 1.f));
        float q2 = rintf(fminf(fmaxf(v.z * inv, -1.f), 1.f));
        float q3 = rintf(fminf(fmaxf(v.w * inv, -1.f), 1.f));
        uint2 u; u.x = packh2(q0, q1); u.y = packh2(q2, q3);
        reinterpret_cast<uint2*>(dst)[i] = u;
    }
}

__global__ void convert_w(const float* __restrict__ wa, __half* __restrict__ ha,
                          const float* __restrict__ wb, __half* __restrict__ hb, int n4) {
    const float* w = blockIdx.y ? wb : wa;
    __half* h = blockIdx.y ? hb : ha;
    int stride = gridDim.x * blockDim.x;
    for (int i = blockIdx.x * blockDim.x + threadIdx.x; i < n4; i += stride) {
        float4 v = reinterpret_cast<const float4*>(w)[i];
        uint2 u; u.x = packh2(v.x, v.y); u.y = packh2(v.z, v.w);
        reinterpret_cast<uint2*>(h)[i] = u;
    }
}

__global__ void build_combined(const float* zb, const float* za, const float* ze,
                               const float* zm, const float* zs, __half* __restrict__ ch) {
    int idx = blockIdx.x * 256 + threadIdx.x;
    int r = idx >> 9;
    int c4 = (idx & 511) * 4;
    const float* src; int off;
    if      (c4 < DB)                { src = zb; off = r * DB + c4; }
    else if (c4 < DB + DA)           { src = za; off = r * DA + (c4 - DB); }
    else if (c4 < DB + DA + DE)      { src = ze; off = r * DE + (c4 - DB - DA); }
    else if (c4 < DB + DA + DE + DM) { src = zm; off = r * DM + (c4 - DB - DA - DE); }
    else                             { src = zs; off = r * DS + (c4 - DB - DA - DE - DM); }
    float4 v = *reinterpret_cast<const float4*>(src + off);
    uint2 u;
    u.x = packh2(v.x, v.y);
    u.y = packh2(v.z, v.w);
    *reinterpret_cast<uint2*>(&ch[(size_t)r * F_DIM + c4]) = u;
}

// fused = LN(sigmoid(1.2 g) * t) -> fp16 (single buffer: mlp input AND residual)
__global__ void fused_sig_ln(const __half* __restrict__ g, const __half* __restrict__ t,
                             const float* __restrict__ lg, const float* __restrict__ lb,
                             __half* __restrict__ fh) {
    int row = blockIdx.x;
    size_t base = (size_t)row * F_DIM;
    float v[8], s1 = 0.f, s2 = 0.f;
#pragma unroll
    for (int i = 0; i < 8; i++) {
        int c = i * 256 + threadIdx.x;
        float gg = __half2float(g[base + c]), tt = __half2float(t[base + c]);
        float f = tt / (1.0f + expf(-1.2f * gg));
        v[i] = f; s1 += f; s2 += f * f;
    }
    __shared__ float rs[8], rq[8];
    int wd = threadIdx.x >> 5, ln = threadIdx.x & 31;
    float a = warpSum(s1), b = warpSum(s2);
    if (ln == 0) { rs[wd] = a; rq[wd] = b; }
    __syncthreads();
    if (wd == 0) {
        float x = (ln < 8) ? rs[ln] : 0.f;
        float y = (ln < 8) ? rq[ln] : 0.f;
        x = warpSum(x); y = warpSum(y);
        if (ln == 0) { rs[0] = x; rq[0] = y; }
    }
    __syncthreads();
    float mean = rs[0] * (1.0f / F_DIM);
    float var = rq[0] * (1.0f / F_DIM) - mean * mean;
    float inv = rsqrtf(var + 1e-5f);
#pragma unroll
    for (int i = 0; i < 8; i++) {
        int c = i * 256 + threadIdx.x;
        float y = (v[i] - mean) * inv * lg[c] + lb[c];
        fh[base + c] = __float2half_rn(y);
    }
}

__global__ void final_ln(const __half* __restrict__ fused, const __half* __restrict__ mlp,
                         const float* __restrict__ lg, const float* __restrict__ lb,
                         float* __restrict__ out) {
    int row = blockIdx.x;
    size_t base = (size_t)row * F_DIM;
    float v[8], s1 = 0.f, s2 = 0.f;
#pragma unroll
    for (int i = 0; i < 8; i++) {
        int c = i * 256 + threadIdx.x;
        float f = __half2float(fused[base + c]) + __half2float(mlp[base + c]);
        v[i] = f; s1 += f; s2 += f * f;
    }
    __shared__ float rs[8], rq[8];
    int wd = threadIdx.x >> 5, ln = threadIdx.x & 31;
    float a = warpSum(s1), b = warpSum(s2);
    if (ln == 0) { rs[wd] = a; rq[wd] = b; }
    __syncthreads();
    if (wd == 0) {
        float x = (ln < 8) ? rs[ln] : 0.f;
        float y = (ln < 8) ? rq[ln] : 0.f;
        x = warpSum(x); y = warpSum(y);
        if (ln == 0) { rs[0] = x; rq[0] = y; }
    }
    __syncthreads();
    float mean = rs[0] * (1.0f / F_DIM);
    float var = rq[0] * (1.0f / F_DIM) - mean * mean;
    float inv = rsqrtf(var + 1e-5f);
#pragma unroll
    for (int i = 0; i < 8; i++) {
        int c = i * 256 + threadIdx.x;
        out[base + c] = (v[i] - mean) * inv * lg[c] + lb[c];
    }
}

// ---- launch ----
extern "C" void kernel_launch(void* const* d_in, const int* in_sizes, int n_in,
                              void* d_out, int out_size) {
    (void)in_sizes; (void)n_in; (void)out_size;
    const float* zb = (const float*)d_in[0];
    const float* za = (const float*)d_in[1];
    const float* ze = (const float*)d_in[2];
    const float* zm = (const float*)d_in[3];
    const float* zs = (const float*)d_in[4];
    const float* gate_w1 = (const float*)d_in[5];
    const float* gate_b1 = (const float*)d_in[6];
    const float* gate_w2 = (const float*)d_in[7];
    const float* gate_b2 = (const float*)d_in[8];
    const float* tr_w1 = (const float*)d_in[9];
    const float* tr_b1 = (const float*)d_in[10];
    const float* tr_w2 = (const float*)d_in[11];
    const float* tr_b2 = (const float*)d_in[12];
    const float* mlp_w1 = (const float*)d_in[13];
    const float* mlp_b1 = (const float*)d_in[14];
    const float* mlp_w2 = (const float*)d_in[15];
    const float* mlp_b2 = (const float*)d_in[16];
    const float* ln1_g = (const float*)d_in[17];
    const float* ln1_b = (const float*)d_in[18];
    const float* ln2_g = (const float*)d_in[19];
    const float* ln2_b = (const float*)d_in[20];
    float* out = (float*)d_out;

    __half *ch, *ah, *ga, *gb, *wqb, *w1h, *w2h;
    float *scb;
    cudaGetSymbolAddress((void**)&ch,  g_comb);
    cudaGetSymbolAddress((void**)&ah,  g_act);
    cudaGetSymbolAddress((void**)&ga,  g_ga);
    cudaGetSymbolAddress((void**)&gb,  g_gb);
    cudaGetSymbolAddress((void**)&wqb, g_wq);
    cudaGetSymbolAddress((void**)&w1h, g_w1h);
    cudaGetSymbolAddress((void**)&w2h, g_w2h);
    cudaGetSymbolAddress((void**)&scb, g_scale);

    cudaFuncSetAttribute(gemm_f16<0>, cudaFuncAttributeMaxDynamicSharedMemorySize, GEMM_SMEM_DYN);
    cudaFuncSetAttribute(gemm_f16<1>, cudaFuncAttributeMaxDynamicSharedMemorySize, GEMM_SMEM_DYN);

    // weight prep (slot order: gate_w1, tr_w1, gate_w2, tr_w2)
    absmean_partial<<<dim3(64, 4), 256>>>(gate_w1, tr_w1, gate_w2, tr_w2);
    quantize_ternary<<<dim3(128, 4), 256>>>(gate_w1, tr_w1, gate_w2, tr_w2, wqb);
    convert_w<<<dim3(512, 2), 256>>>(mlp_w1, w1h, mlp_w2, w2h, (F2_DIM * F_DIM) / 4);
    build_combined<<<(B_ROWS * 512) / 256, 256>>>(zb, za, ze, zm, zs, ch);

    dim3 gDual(F2_DIM / TILE_N, B_ROWS / TILE_M);  // (32, 64)
    dim3 gHalf(F_DIM / TILE_N, B_ROWS / TILE_M);   // (16, 64)

    // layer-1 dual: gate1 + tr1 (shared A; stacked weight slots 0-1; gelu -> act [8192,4096])
    gemm_f16<0><<<gDual, 256, GEMM_SMEM_DYN>>>(ch, F_DIM, 0, wqb, F_DIM,
        scb + 0, gate_b1, tr_b1, nullptr, nullptr, ah, F2_DIM);
    // layer-2 dual: gate2 + tr2 (per-half A window; slots 2-3; fp16 -> ga / gb)
    gemm_f16<1><<<gDual, 256, GEMM_SMEM_DYN>>>(ah, F2_DIM, F_DIM,
        wqb + 2 * (size_t)F_DIM * F_DIM, F_DIM,
        scb + 2, gate_b2, tr_b2, ga, gb, nullptr, 0);
    // sigmoid-gate fuse + ln1 -> fp16 fused (reuses comb buffer; mlp input AND residual)
    fused_sig_ln<<<B_ROWS, 256>>>(ga, gb, ln1_g, ln1_b, ch);
    // mlp1 (gelu -> act [8192,4096])
    gemm_f16<0><<<gDual, 256, GEMM_SMEM_DYN>>>(ch, F_DIM, 0, w1h, F_DIM,
        nullptr, mlp_b1, mlp_b1 + F_DIM, nullptr, nullptr, ah, F2_DIM);
    // mlp2 (K=4096, fp16 -> ga)
    gemm_f16<1><<<gHalf, 256, GEMM_SMEM_DYN>>>(ah, F2_DIM, 0, w2h, F2_DIM,
        nullptr, mlp_b2, mlp_b2, ga, ga, nullptr, 0);
    // residual + ln2
    final_ln<<<B_ROWS, 256>>>(ch, ga, ln2_g, ln2_b, out);
}

// round 16
// speedup vs baseline: 1.0839x; 1.0004x over previous
#include <cuda_runtime.h>
#include <cuda_fp16.h>
#include <cstdint>
#include <math.h>

#define B_ROWS 8192
#define F_DIM  2048
#define F2_DIM 4096
#define DB 512
#define DA 256
#define DE 256
#define DM 512
#define DS 512

// ---- device scratch (allocation forbidden) ----
__device__ __align__(256) __half g_comb[B_ROWS * F_DIM];     // combined, later fused (fp16)
__device__ __align__(256) __half g_act [B_ROWS * F2_DIM];    // layer-1 / mlp1 outputs
__device__ __align__(256) __half g_ga  [B_ROWS * F_DIM];     // gate2 out, later mlp2 out
__device__ __align__(256) __half g_gb  [B_ROWS * F_DIM];     // tr2 out
__device__ __align__(256) __half g_wq[4 * F_DIM * F_DIM];    // slots: gate_w1, tr_w1, gate_w2, tr_w2
__device__ __align__(256) __half g_w1h[F2_DIM * F_DIM];
__device__ __align__(256) __half g_w2h[F_DIM * F2_DIM];
__device__ float g_partials[4 * 64];
__device__ float g_scale[4];

// ---- helpers (baseline PTX only) ----
__device__ __forceinline__ uint32_t smem_u32(const void* p) {
    uint32_t a;
    asm("{ .reg .u64 t; cvta.to.shared.u64 t, %1; cvt.u32.u64 %0, t; }" : "=r"(a) : "l"(p));
    return a;
}
__device__ __forceinline__ uint32_t sw128(uint32_t x) { return x ^ ((x >> 3) & 0x70); }
__device__ __forceinline__ void cp16(uint32_t dst, const void* src) {
    asm volatile("cp.async.cg.shared.global [%0], [%1], 16;\n" :: "r"(dst), "l"(src) : "memory");
}
__device__ __forceinline__ void cp_commit() { asm volatile("cp.async.commit_group;\n" ::: "memory"); }
template <int N> __device__ __forceinline__ void cp_wait() {
    asm volatile("cp.async.wait_group %0;\n" :: "n"(N) : "memory");
}
__device__ __forceinline__ void ldsm4(uint32_t* r, uint32_t a) {
    asm volatile("ldmatrix.sync.aligned.m8n8.x4.shared.b16 {%0,%1,%2,%3}, [%4];"
        : "=r"(r[0]), "=r"(r[1]), "=r"(r[2]), "=r"(r[3]) : "r"(a));
}
__device__ __forceinline__ void mma_f16(float* c, const uint32_t* a, uint32_t b0, uint32_t b1) {
    asm volatile("mma.sync.aligned.m16n8k16.row.col.f32.f16.f16.f32 "
        "{%0,%1,%2,%3}, {%4,%5,%6,%7}, {%8,%9}, {%0,%1,%2,%3};"
        : "+f"(c[0]), "+f"(c[1]), "+f"(c[2]), "+f"(c[3])
        : "r"(a[0]), "r"(a[1]), "r"(a[2]), "r"(a[3]), "r"(b0), "r"(b1));
}
__device__ __forceinline__ float gelu_erf(float h) {
    return 0.5f * h * (1.0f + erff(h * 0.70710678f));
}
__device__ __forceinline__ uint32_t packh2(float a, float b) {
    __half2 v; v.x = __float2half_rn(a); v.y = __float2half_rn(b);
    return *reinterpret_cast<uint32_t*>(&v);
}

// ---- fp16 GEMM, CTA tile 128x128, 256 threads, occ 2 (proven config — unchanged) ----
#define TILE_M 128
#define TILE_N 128
#define TILE_K 64
#define STAGE_BYTES (TILE_M * 128 + TILE_N * 128)   // 32KB
#define STAGES 3
#define GEMM_SMEM_DYN (STAGES * STAGE_BYTES + 1024)

__device__ __forceinline__ void load_tiles(uint32_t sa, uint32_t sb,
        const __half* Ab, const __half* Bt, int m0, int k0, int lda, int K, int tid) {
    const char* ab = (const char*)(Ab + (size_t)m0 * lda + k0);
    const char* bb = (const char*)(Bt + k0);
    size_t ra = (size_t)lda * 2, rb = (size_t)K * 2;
#pragma unroll
    for (int i = 0; i < 4; i++) {
        int t = tid + i * 256, row = t >> 3, ch = t & 7;
        cp16(sa + sw128(row * 128 + ch * 16), ab + (size_t)row * ra + ch * 16);
    }
#pragma unroll
    for (int i = 0; i < 4; i++) {
        int t = tid + i * 256, row = t >> 3, ch = t & 7;
        cp16(sb + sw128(row * 128 + ch * 16), bb + (size_t)row * rb + ch * 16);
    }
}

// EPI 0: gelu -> fp16 at GLOBAL col, stride outStride; EPI 1: linear -> fp16 at LOCAL col, stride F_DIM
template <int EPI>
__global__ void __launch_bounds__(256, 2)
gemm_f16(const __half* A, int lda, int aoffHalf,
         const __half* Bbase, int K,
         const float* scales,
         const float* __restrict__ bias0, const float* __restrict__ bias1,
         __half* outF0, __half* outF1, __half* outH, int outStride) {
    extern __shared__ char smem[];
    uint32_t sbase = (smem_u32(smem) + 1023) & ~1023u;
    int tid = threadIdx.x, wid = tid >> 5, lane = tid & 31;
    int n0 = blockIdx.x * TILE_N, m0 = blockIdx.y * TILE_M;
    int half = (n0 >= F_DIM) ? 1 : 0;
    const __half* Ab = A + (half ? (size_t)aoffHalf : 0);
    const __half* Bt = Bbase + (size_t)n0 * K;
    const float* bias = half ? bias1 : bias0;
    __half* outF = half ? outF1 : outF0;
    int colBiasOff = half * F_DIM;
    int wm = wid & 1, wn = wid >> 1;
    const int iters = K / TILE_K;

    for (int p = 0; p < 2 && p < iters; ++p) {
        uint32_t st = sbase + p * STAGE_BYTES;
        load_tiles(st, st + TILE_M * 128, Ab, Bt, m0, p * TILE_K, lda, K, tid);
        cp_commit();
    }

    float acc[4][4][4];
#pragma unroll
    for (int i = 0; i < 4; i++)
#pragma unroll
        for (int j = 0; j < 4; j++)
#pragma unroll
            for (int k = 0; k < 4; k++) acc[i][j][k] = 0.f;

    int q = lane >> 3, r = lane & 7;
    int aRow = wm * 64 + r + (q & 1) * 8;
    int aCol = (q >> 1) * 16;
    int bRow = wn * 32 + r + (q >> 1) * 8;
    int bCol = (q & 1) * 16;

    for (int it = 0; it < iters; ++it) {
        cp_wait<1>();
        __syncthreads();
        if (it + 2 < iters) {
            uint32_t st = sbase + ((it + 2) % STAGES) * STAGE_BYTES;
            load_tiles(st, st + TILE_M * 128, Ab, Bt, m0, (it + 2) * TILE_K, lda, K, tid);
        }
        cp_commit();
        uint32_t sA = sbase + (it % STAGES) * STAGE_BYTES;
        uint32_t sB = sA + TILE_M * 128;
#pragma unroll
        for (int ks = 0; ks < 4; ++ks) {
            uint32_t a[4][4], b[2][4];
#pragma unroll
            for (int mi = 0; mi < 4; ++mi)
                ldsm4(a[mi], sA + sw128((aRow + mi * 16) * 128 + aCol + ks * 32));
#pragma unroll
            for (int nj = 0; nj < 2; ++nj)
                ldsm4(b[nj], sB + sw128((bRow + nj * 16) * 128 + bCol + ks * 32));
#pragma unroll
            for (int mi = 0; mi < 4; ++mi)
#pragma unroll
                for (int n8 = 0; n8 < 4; ++n8)
                    mma_f16(acc[mi][n8], a[mi],
                            b[n8 >> 1][(n8 & 1) * 2], b[n8 >> 1][(n8 & 1) * 2 + 1]);
        }
    }

    float sc = scales ? scales[half] : 1.0f;
    int group = lane >> 2, tg = lane & 3;
#pragma unroll
    for (int mi = 0; mi < 4; ++mi) {
#pragma unroll
        for (int n8 = 0; n8 < 4; ++n8) {
            int row = m0 + wm * 64 + mi * 16 + group;
            int col = n0 + wn * 32 + n8 * 8 + tg * 2;
            int cl = col - colBiasOff;
            float bb0 = bias[cl], bb1 = bias[cl + 1];
            float y0 = fmaf(sc, acc[mi][n8][0], bb0);
            float y1 = fmaf(sc, acc[mi][n8][1], bb1);
            float y2 = fmaf(sc, acc[mi][n8][2], bb0);
            float y3 = fmaf(sc, acc[mi][n8][3], bb1);
            if (EPI == 0) {
                *(uint32_t*)&outH[(size_t)row * outStride + col]       = packh2(gelu_erf(y0), gelu_erf(y1));
                *(uint32_t*)&outH[(size_t)(row + 8) * outStride + col] = packh2(gelu_erf(y2), gelu_erf(y3));
            } else {
                *(uint32_t*)&outF[(size_t)row * F_DIM + cl]       = packh2(y0, y1);
                *(uint32_t*)&outF[(size_t)(row + 8) * F_DIM + cl] = packh2(y2, y3);
            }
        }
    }
}

// ---- elementwise ----
__device__ __forceinline__ float warpSum(float x) {
#pragma unroll
    for (int o = 16; o > 0; o >>= 1) x += __shfl_xor_sync(0xffffffffu, x, o);
    return x;
}

// prep1: blocks [0,16384) build_combined ; [16384, 16384+256) absmean (4 slots x 64 blocks)
__global__ void prep1(const float* zb, const float* za, const float* ze,
                      const float* zm, const float* zs, __half* __restrict__ ch,
                      const float* w0, const float* w1, const float* w2, const float* w3) {
    int bx = blockIdx.x;
    if (bx < 16384) {
        int idx = bx * 256 + threadIdx.x;
        int r = idx >> 9;
        int c4 = (idx & 511) * 4;
        const float* src; int off;
        if      (c4 < DB)                { src = zb; off = r * DB + c4; }
        else if (c4 < DB + DA)           { src = za; off = r * DA + (c4 - DB); }
        else if (c4 < DB + DA + DE)      { src = ze; off = r * DE + (c4 - DB - DA); }
        else if (c4 < DB + DA + DE + DM) { src = zm; off = r * DM + (c4 - DB - DA - DE); }
        else                             { src = zs; off = r * DS + (c4 - DB - DA - DE - DM); }
        float4 v = *reinterpret_cast<const float4*>(src + off);
        uint2 u;
        u.x = packh2(v.x, v.y);
        u.y = packh2(v.z, v.w);
        *reinterpret_cast<uint2*>(&ch[(size_t)r * F_DIM + c4]) = u;
    } else {
        int t = bx - 16384;
        int slot = t >> 6, blk = t & 63;
        const float* w = (slot == 0) ? w0 : (slot == 1) ? w1 : (slot == 2) ? w2 : w3;
        const int chunk = (F_DIM * F_DIM) / 64;
        int base = blk * chunk;
        float s = 0.f;
        for (int i = threadIdx.x; i < chunk; i += 256) s += fabsf(w[base + i]);
        __shared__ float red[8];
        s = warpSum(s);
        int wd = threadIdx.x >> 5, ln = threadIdx.x & 31;
        if (ln == 0) red[wd] = s;
        __syncthreads();
        if (wd == 0) {
            float v = (ln < 8) ? red[ln] : 0.f;
            v = warpSum(v);
            if (ln == 0) g_partials[slot * 64 + blk] = v;
        }
    }
}

// prep2: blocks [0,2048) convert mlp weights (1024 each) ; [2048, 2048+512) quantize ternary (4 x 128)
__global__ void prep2(const float* mw1, __half* __restrict__ h1,
                      const float* mw2, __half* __restrict__ h2,
                      const float* w0, const float* w1, const float* w2, const float* w3,
                      __half* __restrict__ kq) {
    int bx = blockIdx.x;
    if (bx < 2048) {
        const float* w = (bx < 1024) ? mw1 : mw2;
        __half* h = (bx < 1024) ? h1 : h2;
        int b = (bx < 1024) ? bx : bx - 1024;
        const int n4 = (F2_DIM * F_DIM) / 4;
        int stride = 1024 * 256;
        for (int i = b * 256 + threadIdx.x; i < n4; i += stride) {
            float4 v = reinterpret_cast<const float4*>(w)[i];
            uint2 u; u.x = packh2(v.x, v.y); u.y = packh2(v.z, v.w);
            reinterpret_cast<uint2*>(h)[i] = u;
        }
    } else {
        int t = bx - 2048;
        int slot = t >> 7, blk = t & 127;
        const float* w = (slot == 0) ? w0 : (slot == 1) ? w1 : (slot == 2) ? w2 : w3;
        __half* dst = kq + (size_t)slot * F_DIM * F_DIM;
        float sum = 0.f;
#pragma unroll
        for (int i = 0; i < 64; i++) sum += g_partials[slot * 64 + i];
        float s = sum * (1.0f / (float)(F_DIM * F_DIM));
        if (blk == 0 && threadIdx.x == 0) g_scale[slot] = s;
        float inv = 1.0f / (s + 1e-5f);
        const int n4 = (F_DIM * F_DIM) / 4;
        int stride = 128 * 256;
        for (int i = blk * 256 + threadIdx.x; i < n4; i += stride) {
            float4 v = reinterpret_cast<const float4*>(w)[i];
            float q0 = rintf(fminf(fmaxf(v.x * inv, -1.f), 1.f));
            float q1 = rintf(fminf(fmaxf(v.y * inv, -1.f), 1.f));
            float q2 = rintf(fminf(fmaxf(v.z * inv, -1.f), 1.f));
            float q3 = rintf(fminf(fmaxf(v.w * inv, -1.f), 1.f));
            uint2 u; u.x = packh2(q0, q1); u.y = packh2(q2, q3);
            reinterpret_cast<uint2*>(dst)[i] = u;
        }
    }
}

// fused = LN(sigmoid(1.2 g) * t) -> fp16 (single buffer: mlp input AND residual)
__global__ void fused_sig_ln(const __half* __restrict__ g, const __half* __restrict__ t,
                             const float* __restrict__ lg, const float* __restrict__ lb,
                             __half* __restrict__ fh) {
    int row = blockIdx.x;
    size_t base = (size_t)row * F_DIM;
    float v[8], s1 = 0.f, s2 = 0.f;
#pragma unroll
    for (int i = 0; i < 8; i++) {
        int c = i * 256 + threadIdx.x;
        float gg = __half2float(g[base + c]), tt = __half2float(t[base + c]);
        float f = tt / (1.0f + expf(-1.2f * gg));
        v[i] = f; s1 += f; s2 += f * f;
    }
    __shared__ float rs[8], rq[8];
    int wd = threadIdx.x >> 5, ln = threadIdx.x & 31;
    float a = warpSum(s1), b = warpSum(s2);
    if (ln == 0) { rs[wd] = a; rq[wd] = b; }
    __syncthreads();
    if (wd == 0) {
        float x = (ln < 8) ? rs[ln] : 0.f;
        float y = (ln < 8) ? rq[ln] : 0.f;
        x = warpSum(x); y = warpSum(y);
        if (ln == 0) { rs[0] = x; rq[0] = y; }
    }
    __syncthreads();
    float mean = rs[0] * (1.0f / F_DIM);
    float var = rq[0] * (1.0f / F_DIM) - mean * mean;
    float inv = rsqrtf(var + 1e-5f);
#pragma unroll
    for (int i = 0; i < 8; i++) {
        int c = i * 256 + threadIdx.x;
        float y = (v[i] - mean) * inv * lg[c] + lb[c];
        fh[base + c] = __float2half_rn(y);
    }
}

__global__ void final_ln(const __half* __restrict__ fused, const __half* __restrict__ mlp,
                         const float* __restrict__ lg, const float* __restrict__ lb,
                         float* __restrict__ out) {
    int row = blockIdx.x;
    size_t base = (size_t)row * F_DIM;
    float v[8], s1 = 0.f, s2 = 0.f;
#pragma unroll
    for (int i = 0; i < 8; i++) {
        int c = i * 256 + threadIdx.x;
        float f = __half2float(fused[base + c]) + __half2float(mlp[base + c]);
        v[i] = f; s1 += f; s2 += f * f;
    }
    __shared__ float rs[8], rq[8];
    int wd = threadIdx.x >> 5, ln = threadIdx.x & 31;
    float a = warpSum(s1), b = warpSum(s2);
    if (ln == 0) { rs[wd] = a; rq[wd] = b; }
    __syncthreads();
    if (wd == 0) {
        float x = (ln < 8) ? rs[ln] : 0.f;
        float y = (ln < 8) ? rq[ln] : 0.f;
        x = warpSum(x); y = warpSum(y);
        if (ln == 0) { rs[0] = x; rq[0] = y; }
    }
    __syncthreads();
    float mean = rs[0] * (1.0f / F_DIM);
    float var = rq[0] * (1.0f / F_DIM) - mean * mean;
    float inv = rsqrtf(var + 1e-5f);
#pragma unroll
    for (int i = 0; i < 8; i++) {
        int c = i * 256 + threadIdx.x;
        out[base + c] = (v[i] - mean) * inv * lg[c] + lb[c];
    }
}

// ---- launch ----
extern "C" void kernel_launch(void* const* d_in, const int* in_sizes, int n_in,
                              void* d_out, int out_size) {
    (void)in_sizes; (void)n_in; (void)out_size;
    const float* zb = (const float*)d_in[0];
    const float* za = (const float*)d_in[1];
    const float* ze = (const float*)d_in[2];
    const float* zm = (const float*)d_in[3];
    const float* zs = (const float*)d_in[4];
    const float* gate_w1 = (const float*)d_in[5];
    const float* gate_b1 = (const float*)d_in[6];
    const float* gate_w2 = (const float*)d_in[7];
    const float* gate_b2 = (const float*)d_in[8];
    const float* tr_w1 = (const float*)d_in[9];
    const float* tr_b1 = (const float*)d_in[10];
    const float* tr_w2 = (const float*)d_in[11];
    const float* tr_b2 = (const float*)d_in[12];
    const float* mlp_w1 = (const float*)d_in[13];
    const float* mlp_b1 = (const float*)d_in[14];
    const float* mlp_w2 = (const float*)d_in[15];
    const float* mlp_b2 = (const float*)d_in[16];
    const float* ln1_g = (const float*)d_in[17];
    const float* ln1_b = (const float*)d_in[18];
    const float* ln2_g = (const float*)d_in[19];
    const float* ln2_b = (const float*)d_in[20];
    float* out = (float*)d_out;

    __half *ch, *ah, *ga, *gb, *wqb, *w1h, *w2h;
    float *scb;
    cudaGetSymbolAddress((void**)&ch,  g_comb);
    cudaGetSymbolAddress((void**)&ah,  g_act);
    cudaGetSymbolAddress((void**)&ga,  g_ga);
    cudaGetSymbolAddress((void**)&gb,  g_gb);
    cudaGetSymbolAddress((void**)&wqb, g_wq);
    cudaGetSymbolAddress((void**)&w1h, g_w1h);
    cudaGetSymbolAddress((void**)&w2h, g_w2h);
    cudaGetSymbolAddress((void**)&scb, g_scale);

    cudaFuncSetAttribute(gemm_f16<0>, cudaFuncAttributeMaxDynamicSharedMemorySize, GEMM_SMEM_DYN);
    cudaFuncSetAttribute(gemm_f16<1>, cudaFuncAttributeMaxDynamicSharedMemorySize, GEMM_SMEM_DYN);

    // prep1: build_combined || absmean  (slot order: gate_w1, tr_w1, gate_w2, tr_w2)
    prep1<<<16384 + 256, 256>>>(zb, za, ze, zm, zs, ch, gate_w1, tr_w1, gate_w2, tr_w2);
    // prep2: convert mlp weights || quantize ternary
    prep2<<<2048 + 512, 256>>>(mlp_w1, w1h, mlp_w2, w2h, gate_w1, tr_w1, gate_w2, tr_w2, wqb);

    dim3 gDual(F2_DIM / TILE_N, B_ROWS / TILE_M);  // (32, 64)
    dim3 gHalf(F_DIM / TILE_N, B_ROWS / TILE_M);   // (16, 64)

    // layer-1 dual: gate1 + tr1 (shared A; stacked weight slots 0-1; gelu -> act [8192,4096])
    gemm_f16<0><<<gDual, 256, GEMM_SMEM_DYN>>>(ch, F_DIM, 0, wqb, F_DIM,
        scb + 0, gate_b1, tr_b1, nullptr, nullptr, ah, F2_DIM);
    // layer-2 dual: gate2 + tr2 (per-half A window; slots 2-3; fp16 -> ga / gb)
    gemm_f16<1><<<gDual, 256, GEMM_SMEM_DYN>>>(ah, F2_DIM, F_DIM,
        wqb + 2 * (size_t)F_DIM * F_DIM, F_DIM,
        scb + 2, gate_b2, tr_b2, ga, gb, nullptr, 0);
    // sigmoid-gate fuse + ln1 -> fp16 fused (reuses comb buffer; mlp input AND residual)
    fused_sig_ln<<<B_ROWS, 256>>>(ga, gb, ln1_g, ln1_b, ch);
    // mlp1 (gelu -> act [8192,4096])
    gemm_f16<0><<<gDual, 256, GEMM_SMEM_DYN>>>(ch, F_DIM, 0, w1h, F_DIM,
        nullptr, mlp_b1, mlp_b1 + F_DIM, nullptr, nullptr, ah, F2_DIM);
    // mlp2 (K=4096, fp16 -> ga)
    gemm_f16<1><<<gHalf, 256, GEMM_SMEM_DYN>>>(ah, F2_DIM, 0, w2h, F2_DIM,
        nullptr, mlp_b2, mlp_b2, ga, ga, nullptr, 0);
    // residual + ln2
    final_ln<<<B_ROWS, 256>>>(ch, ga, ln2_g, ln2_b, out);
}